// round 4
// baseline (speedup 1.0000x reference)
#include <cuda_runtime.h>
#include <cstdint>

#define N_NODES   8192
#define THREADS   256
#define GRID      592              // persistent; 4 CTA/SM target
#define NBINS     256
#define CAND_MAX  1024
#define NGROUPS   64               // 4-lane group maxima (256 thr / 4)
#define VEC_ITERS (N_NODES / 4 / THREADS)   // 8 float4 per thread

// Monotonic float -> uint mapping (larger float => larger uint). No NaNs in inputs.
__device__ __forceinline__ uint32_t f2ord(float f) {
    uint32_t u = __float_as_uint(f);
    return u ^ ((uint32_t)((int32_t)u >> 31) | 0x80000000u);
}

// Unique 48-bit total-order key: ties in value resolve to the smaller index
// (matching jax.lax.top_k).
__device__ __forceinline__ unsigned long long make_key(uint32_t ord, uint32_t j) {
    return ((unsigned long long)ord << 16) | (unsigned)(N_NODES - 1 - j);
}

__device__ __forceinline__ void pf_l2(const float* p) {
    asm volatile("prefetch.global.L2 [%0];" :: "l"(p));
}

// Fallback-only: suffix-sum a 256-bin histogram, pick bin holding krem-th largest.
__device__ __forceinline__ void scan_pick(const uint32_t* hist,
                                          volatile uint32_t* s_cum,
                                          unsigned long long* s_prefix,
                                          int* s_krem)
{
    const int lane = threadIdx.x;           // caller guarantees tid < 32
    uint32_t h[8], suf[8];
    #pragma unroll
    for (int j = 0; j < 8; ++j) h[j] = hist[lane * 8 + j];
    uint32_t acc = 0;
    #pragma unroll
    for (int j = 7; j >= 0; --j) { acc += h[j]; suf[j] = acc; }
    uint32_t run = acc;
    #pragma unroll
    for (int off = 1; off < 32; off <<= 1) {
        uint32_t v = __shfl_down_sync(0xFFFFFFFFu, run, off);
        if (lane + off < 32) run += v;
    }
    const uint32_t above = run - acc;
    #pragma unroll
    for (int j = 0; j < 8; ++j) s_cum[lane * 8 + j] = above + suf[j];
    if (lane == 0) s_cum[NBINS] = 0;
    __syncwarp();
    const uint32_t krem = (uint32_t)(*s_krem);
    #pragma unroll
    for (int j = 0; j < 8; ++j) {
        const int b = lane * 8 + j;
        const uint32_t ge = s_cum[b];
        const uint32_t gt = s_cum[b + 1];
        if (ge >= krem && gt < krem) {
            *s_prefix = (*s_prefix << 8) | (unsigned long long)(uint32_t)b;
            *s_krem   = (int)(krem - gt);
        }
    }
}

__global__ __launch_bounds__(THREADS, 4)
void st_subset_sampler_kernel(const float* __restrict__ scores,
                              const float* __restrict__ noise,
                              const float* __restrict__ tau_p,
                              const int*   __restrict__ k_p,
                              float* __restrict__ out)
{
    __shared__ uint32_t s_ord[N_NODES];            // 32 KB; fallback + insurance
    __shared__ uint32_t s_gmax[NGROUPS];
    __shared__ unsigned long long s_ckey[CAND_MAX];// candidate keys (8 KB)
    __shared__ int      s_ncand;
    __shared__ uint32_t s_t32;
    // fallback-only state
    __shared__ uint32_t s_hist[NBINS];
    __shared__ uint32_t s_cum[NBINS + 1];
    __shared__ unsigned long long s_prefix;
    __shared__ int      s_krem;

    const int tid = threadIdx.x;
    const float tau = __ldg(tau_p);
    const int   k   = __ldg(k_p);

    // Power-of-two tau => a/tau == a*(1/tau) exactly; mul-then-add matches the
    // reference rounding bit-for-bit. Otherwise exact fdiv fallback.
    const uint32_t tb = __float_as_uint(tau);
    const bool pow2 = ((tb & 0x007FFFFFu) == 0u) &&
                      ((tb & 0x7F800000u) != 0u) &&
                      ((tb & 0x7F800000u) != 0x7F800000u);
    const float rtau = __frcp_rn(tau);

    for (int row_i = blockIdx.x; row_i < N_NODES; row_i += GRID) {
        const size_t row = (size_t)row_i * N_NODES;
        const float4* sp = reinterpret_cast<const float4*>(scores + row);
        const float4* np = reinterpret_cast<const float4*>(noise  + row);

        if (tid == 0) { s_ncand = 0; s_t32 = 0; }

        // ---- phase 1: load row into REGISTERS, mirror to smem (fallback), max ----
        uint4 o[VEC_ITERS];
        uint32_t m = 0;
        if (pow2) {
            #pragma unroll
            for (int i = 0; i < VEC_ITERS; ++i) {
                const int idx = tid + i * THREADS;
                const float4 a = sp[idx];
                const float4 b = np[idx];
                o[i].x = f2ord(__fadd_rn(__fmul_rn(a.x, rtau), b.x));
                o[i].y = f2ord(__fadd_rn(__fmul_rn(a.y, rtau), b.y));
                o[i].z = f2ord(__fadd_rn(__fmul_rn(a.z, rtau), b.z));
                o[i].w = f2ord(__fadd_rn(__fmul_rn(a.w, rtau), b.w));
                reinterpret_cast<uint4*>(s_ord)[idx] = o[i];
                m = max(m, max(max(o[i].x, o[i].y), max(o[i].z, o[i].w)));
            }
        } else {
            #pragma unroll
            for (int i = 0; i < VEC_ITERS; ++i) {
                const int idx = tid + i * THREADS;
                const float4 a = sp[idx];
                const float4 b = np[idx];
                o[i].x = f2ord(__fadd_rn(__fdiv_rn(a.x, tau), b.x));
                o[i].y = f2ord(__fadd_rn(__fdiv_rn(a.y, tau), b.y));
                o[i].z = f2ord(__fadd_rn(__fdiv_rn(a.z, tau), b.z));
                o[i].w = f2ord(__fadd_rn(__fdiv_rn(a.w, tau), b.w));
                reinterpret_cast<uint4*>(s_ord)[idx] = o[i];
                m = max(m, max(max(o[i].x, o[i].y), max(o[i].z, o[i].w)));
            }
        }

        // L2-prefetch next row (this CTA's next stripe) to keep DRAM streaming
        // through the select phases. 74 MB aggregate — fits L2.
        const int row_next = row_i + GRID;
        if (row_next < N_NODES) {
            const float* pfs = scores + (size_t)row_next * N_NODES;
            const float* pfn = noise  + (size_t)row_next * N_NODES;
            #pragma unroll
            for (int l = 0; l < 2; ++l) {
                const size_t off = ((size_t)tid * 2 + l) * 32;   // 128B lines
                pf_l2(pfs + off);
                pf_l2(pfn + off);
            }
        }

        // 4-lane group max -> 64 group maxima
        m = max(m, __shfl_down_sync(0xFFFFFFFFu, m, 2, 4));
        m = max(m, __shfl_down_sync(0xFFFFFFFFu, m, 1, 4));
        if ((tid & 3) == 0) s_gmax[tid >> 2] = m;
        __syncthreads();

        // ---- phase 2: warp 0 exact-ranks the 64 group maxima ----
        // t32 = k-th largest group max <= true k-th largest element T.
        if (tid < 32 && k >= 1 && k <= NGROUPS) {
            const uint32_t v0 = s_gmax[tid];
            const uint32_t v1 = s_gmax[tid + 32];
            int r0 = 0, r1 = 0;
            #pragma unroll 8
            for (int j = 0; j < NGROUPS; ++j) {
                const uint32_t w = s_gmax[j];
                r0 += (w > v0) || (w == v0 && j < tid);
                r1 += (w > v1) || (w == v1 && j < tid + 32);
            }
            if (r0 == k - 1) s_t32 = v0;
            if (r1 == k - 1) s_t32 = v1;
        }
        __syncthreads();
        const uint32_t t32 = s_t32;

        // ---- phase 3: provisional write + candidate push, all from registers ----
        float4* op = reinterpret_cast<float4*>(out + row);
        #pragma unroll
        for (int i = 0; i < VEC_ITERS; ++i) {
            const int idx = tid + i * THREADS;
            float4 r;
            r.x = (o[i].x >= t32) ? 1.0f : 0.0f;
            r.y = (o[i].y >= t32) ? 1.0f : 0.0f;
            r.z = (o[i].z >= t32) ? 1.0f : 0.0f;
            r.w = (o[i].w >= t32) ? 1.0f : 0.0f;
            op[idx] = r;
            const uint32_t j = (uint32_t)idx * 4;
            if (o[i].x >= t32) { int p = atomicAdd(&s_ncand, 1); if (p < CAND_MAX) s_ckey[p] = make_key(o[i].x, j + 0); }
            if (o[i].y >= t32) { int p = atomicAdd(&s_ncand, 1); if (p < CAND_MAX) s_ckey[p] = make_key(o[i].y, j + 1); }
            if (o[i].z >= t32) { int p = atomicAdd(&s_ncand, 1); if (p < CAND_MAX) s_ckey[p] = make_key(o[i].z, j + 2); }
            if (o[i].w >= t32) { int p = atomicAdd(&s_ncand, 1); if (p < CAND_MAX) s_ckey[p] = make_key(o[i].w, j + 3); }
        }
        __syncthreads();
        const int nc = s_ncand;

        if (nc <= CAND_MAX) {
            // ---- phase 4: O(nc^2) exact rank over candidates (nc ~ k) ----
            for (int c = tid; c < nc; c += THREADS) {
                const unsigned long long key = s_ckey[c];
                int rank = 0;
                for (int t = 0; t < nc; ++t)
                    rank += (s_ckey[t] > key);
                const uint32_t j = (uint32_t)(N_NODES - 1) - (uint32_t)(key & 0xFFFFu);
                out[row + j] = (rank < k) ? 1.0f : 0.0f;
            }
        } else {
            // ---- fallback (adversarial inputs only): exact 48-bit radix ----
            if (tid == 0) { s_prefix = 0ull; s_krem = k; }
            for (int d = 0; d < 6; ++d) {
                if (tid < NBINS) s_hist[tid] = 0;
                __syncthreads();
                const unsigned long long pre = s_prefix;
                const int shd = 40 - 8 * d, shp = 48 - 8 * d;
                for (int jj = tid; jj < N_NODES; jj += THREADS) {
                    const unsigned long long key = make_key(s_ord[jj], (uint32_t)jj);
                    if (d == 0 || (key >> shp) == pre)
                        atomicAdd(&s_hist[(uint32_t)(key >> shd) & 0xFFu], 1u);
                }
                __syncthreads();
                if (tid < 32) scan_pick(s_hist, s_cum, &s_prefix, &s_krem);
                __syncthreads();
            }
            const unsigned long long thr = s_prefix;
            for (int jj = tid; jj < N_NODES; jj += THREADS)
                out[row + jj] = (make_key(s_ord[jj], (uint32_t)jj) >= thr) ? 1.0f : 0.0f;
        }
        __syncthreads();   // protect s_ckey / s_ncand / s_gmax reuse next row
    }
}

extern "C" void kernel_launch(void* const* d_in, const int* in_sizes, int n_in,
                              void* d_out, int out_size) {
    (void)in_sizes; (void)n_in; (void)out_size;
    const float* scores = (const float*)d_in[0];
    const float* noise  = (const float*)d_in[1];
    const float* tau    = (const float*)d_in[2];
    const int*   k      = (const int*)d_in[3];
    float* out = (float*)d_out;
    st_subset_sampler_kernel<<<GRID, THREADS>>>(scores, noise, tau, k, out);
}

// round 5
// speedup vs baseline: 1.0027x; 1.0027x over previous
#include <cuda_runtime.h>
#include <cstdint>

#define N_NODES   8192
#define THREADS   256
#define GRID      592              // persistent; 4 CTA/SM target
#define NBINS     256
#define CAND_MAX  1024
#define NGROUPS   64               // 4-lane group maxima (256 thr / 4)
#define VEC_ITERS (N_NODES / 4 / THREADS)   // 8 float4 per thread

// Monotonic float -> uint mapping (larger float => larger uint). No NaNs in inputs.
__device__ __forceinline__ uint32_t f2ord(float f) {
    uint32_t u = __float_as_uint(f);
    return u ^ ((uint32_t)((int32_t)u >> 31) | 0x80000000u);
}

// Unique 48-bit total-order key: ties in value resolve to the smaller index
// (matching jax.lax.top_k).
__device__ __forceinline__ unsigned long long make_key(uint32_t ord, uint32_t j) {
    return ((unsigned long long)ord << 16) | (unsigned)(N_NODES - 1 - j);
}

__device__ __forceinline__ void pf_l2(const float* p) {
    asm volatile("prefetch.global.L2 [%0];" :: "l"(p));
}

// Fallback-only: suffix-sum a 256-bin histogram, pick bin holding krem-th largest.
__device__ __forceinline__ void scan_pick(const uint32_t* hist,
                                          volatile uint32_t* s_cum,
                                          unsigned long long* s_prefix,
                                          int* s_krem)
{
    const int lane = threadIdx.x;           // caller guarantees tid < 32
    uint32_t h[8], suf[8];
    #pragma unroll
    for (int j = 0; j < 8; ++j) h[j] = hist[lane * 8 + j];
    uint32_t acc = 0;
    #pragma unroll
    for (int j = 7; j >= 0; --j) { acc += h[j]; suf[j] = acc; }
    uint32_t run = acc;
    #pragma unroll
    for (int off = 1; off < 32; off <<= 1) {
        uint32_t v = __shfl_down_sync(0xFFFFFFFFu, run, off);
        if (lane + off < 32) run += v;
    }
    const uint32_t above = run - acc;
    #pragma unroll
    for (int j = 0; j < 8; ++j) s_cum[lane * 8 + j] = above + suf[j];
    if (lane == 0) s_cum[NBINS] = 0;
    __syncwarp();
    const uint32_t krem = (uint32_t)(*s_krem);
    #pragma unroll
    for (int j = 0; j < 8; ++j) {
        const int b = lane * 8 + j;
        const uint32_t ge = s_cum[b];
        const uint32_t gt = s_cum[b + 1];
        if (ge >= krem && gt < krem) {
            *s_prefix = (*s_prefix << 8) | (unsigned long long)(uint32_t)b;
            *s_krem   = (int)(krem - gt);
        }
    }
}

__global__ __launch_bounds__(THREADS, 4)
void st_subset_sampler_kernel(const float* __restrict__ scores,
                              const float* __restrict__ noise,
                              const float* __restrict__ tau_p,
                              const int*   __restrict__ k_p,
                              float* __restrict__ out)
{
    __shared__ uint32_t s_ord[N_NODES];            // 32 KB; fallback + insurance
    __shared__ uint32_t s_gmax[NGROUPS];
    __shared__ unsigned long long s_ckey[CAND_MAX];// candidate keys (8 KB)
    __shared__ int      s_ncand;
    __shared__ uint32_t s_t32;
    // fallback-only state
    __shared__ uint32_t s_hist[NBINS];
    __shared__ uint32_t s_cum[NBINS + 1];
    __shared__ unsigned long long s_prefix;
    __shared__ int      s_krem;

    const int tid = threadIdx.x;
    const float tau = __ldg(tau_p);
    const int   k   = __ldg(k_p);

    // Power-of-two tau => a/tau == a*(1/tau) exactly; mul-then-add matches the
    // reference rounding bit-for-bit. Otherwise exact fdiv fallback.
    const uint32_t tb = __float_as_uint(tau);
    const bool pow2 = ((tb & 0x007FFFFFu) == 0u) &&
                      ((tb & 0x7F800000u) != 0u) &&
                      ((tb & 0x7F800000u) != 0x7F800000u);
    const float rtau = __frcp_rn(tau);

    for (int row_i = blockIdx.x; row_i < N_NODES; row_i += GRID) {
        const size_t row = (size_t)row_i * N_NODES;
        const float4* sp = reinterpret_cast<const float4*>(scores + row);
        const float4* np = reinterpret_cast<const float4*>(noise  + row);

        if (tid == 0) { s_ncand = 0; s_t32 = 0; }

        // ---- phase 1: load row into REGISTERS, mirror to smem (fallback), max ----
        uint4 o[VEC_ITERS];
        uint32_t m = 0;
        if (pow2) {
            #pragma unroll
            for (int i = 0; i < VEC_ITERS; ++i) {
                const int idx = tid + i * THREADS;
                const float4 a = sp[idx];
                const float4 b = np[idx];
                o[i].x = f2ord(__fadd_rn(__fmul_rn(a.x, rtau), b.x));
                o[i].y = f2ord(__fadd_rn(__fmul_rn(a.y, rtau), b.y));
                o[i].z = f2ord(__fadd_rn(__fmul_rn(a.z, rtau), b.z));
                o[i].w = f2ord(__fadd_rn(__fmul_rn(a.w, rtau), b.w));
                reinterpret_cast<uint4*>(s_ord)[idx] = o[i];
                m = max(m, max(max(o[i].x, o[i].y), max(o[i].z, o[i].w)));
            }
        } else {
            #pragma unroll
            for (int i = 0; i < VEC_ITERS; ++i) {
                const int idx = tid + i * THREADS;
                const float4 a = sp[idx];
                const float4 b = np[idx];
                o[i].x = f2ord(__fadd_rn(__fdiv_rn(a.x, tau), b.x));
                o[i].y = f2ord(__fadd_rn(__fdiv_rn(a.y, tau), b.y));
                o[i].z = f2ord(__fadd_rn(__fdiv_rn(a.z, tau), b.z));
                o[i].w = f2ord(__fadd_rn(__fdiv_rn(a.w, tau), b.w));
                reinterpret_cast<uint4*>(s_ord)[idx] = o[i];
                m = max(m, max(max(o[i].x, o[i].y), max(o[i].z, o[i].w)));
            }
        }

        // L2-prefetch next row (this CTA's next stripe) to keep DRAM streaming
        // through the select phases. 74 MB aggregate — fits L2.
        const int row_next = row_i + GRID;
        if (row_next < N_NODES) {
            const float* pfs = scores + (size_t)row_next * N_NODES;
            const float* pfn = noise  + (size_t)row_next * N_NODES;
            #pragma unroll
            for (int l = 0; l < 2; ++l) {
                const size_t off = ((size_t)tid * 2 + l) * 32;   // 128B lines
                pf_l2(pfs + off);
                pf_l2(pfn + off);
            }
        }

        // 4-lane group max -> 64 group maxima
        m = max(m, __shfl_down_sync(0xFFFFFFFFu, m, 2, 4));
        m = max(m, __shfl_down_sync(0xFFFFFFFFu, m, 1, 4));
        if ((tid & 3) == 0) s_gmax[tid >> 2] = m;
        __syncthreads();

        // ---- phase 2: warp 0 exact-ranks the 64 group maxima ----
        // t32 = k-th largest group max <= true k-th largest element T.
        if (tid < 32 && k >= 1 && k <= NGROUPS) {
            const uint32_t v0 = s_gmax[tid];
            const uint32_t v1 = s_gmax[tid + 32];
            int r0 = 0, r1 = 0;
            #pragma unroll 8
            for (int j = 0; j < NGROUPS; ++j) {
                const uint32_t w = s_gmax[j];
                r0 += (w > v0) || (w == v0 && j < tid);
                r1 += (w > v1) || (w == v1 && j < tid + 32);
            }
            if (r0 == k - 1) s_t32 = v0;
            if (r1 == k - 1) s_t32 = v1;
        }
        __syncthreads();
        const uint32_t t32 = s_t32;

        // ---- phase 3: provisional write + candidate push, all from registers ----
        float4* op = reinterpret_cast<float4*>(out + row);
        #pragma unroll
        for (int i = 0; i < VEC_ITERS; ++i) {
            const int idx = tid + i * THREADS;
            float4 r;
            r.x = (o[i].x >= t32) ? 1.0f : 0.0f;
            r.y = (o[i].y >= t32) ? 1.0f : 0.0f;
            r.z = (o[i].z >= t32) ? 1.0f : 0.0f;
            r.w = (o[i].w >= t32) ? 1.0f : 0.0f;
            op[idx] = r;
            const uint32_t j = (uint32_t)idx * 4;
            if (o[i].x >= t32) { int p = atomicAdd(&s_ncand, 1); if (p < CAND_MAX) s_ckey[p] = make_key(o[i].x, j + 0); }
            if (o[i].y >= t32) { int p = atomicAdd(&s_ncand, 1); if (p < CAND_MAX) s_ckey[p] = make_key(o[i].y, j + 1); }
            if (o[i].z >= t32) { int p = atomicAdd(&s_ncand, 1); if (p < CAND_MAX) s_ckey[p] = make_key(o[i].z, j + 2); }
            if (o[i].w >= t32) { int p = atomicAdd(&s_ncand, 1); if (p < CAND_MAX) s_ckey[p] = make_key(o[i].w, j + 3); }
        }
        __syncthreads();
        const int nc = s_ncand;

        if (nc <= CAND_MAX) {
            // ---- phase 4: O(nc^2) exact rank over candidates (nc ~ k) ----
            for (int c = tid; c < nc; c += THREADS) {
                const unsigned long long key = s_ckey[c];
                int rank = 0;
                for (int t = 0; t < nc; ++t)
                    rank += (s_ckey[t] > key);
                const uint32_t j = (uint32_t)(N_NODES - 1) - (uint32_t)(key & 0xFFFFu);
                out[row + j] = (rank < k) ? 1.0f : 0.0f;
            }
        } else {
            // ---- fallback (adversarial inputs only): exact 48-bit radix ----
            if (tid == 0) { s_prefix = 0ull; s_krem = k; }
            for (int d = 0; d < 6; ++d) {
                if (tid < NBINS) s_hist[tid] = 0;
                __syncthreads();
                const unsigned long long pre = s_prefix;
                const int shd = 40 - 8 * d, shp = 48 - 8 * d;
                for (int jj = tid; jj < N_NODES; jj += THREADS) {
                    const unsigned long long key = make_key(s_ord[jj], (uint32_t)jj);
                    if (d == 0 || (key >> shp) == pre)
                        atomicAdd(&s_hist[(uint32_t)(key >> shd) & 0xFFu], 1u);
                }
                __syncthreads();
                if (tid < 32) scan_pick(s_hist, s_cum, &s_prefix, &s_krem);
                __syncthreads();
            }
            const unsigned long long thr = s_prefix;
            for (int jj = tid; jj < N_NODES; jj += THREADS)
                out[row + jj] = (make_key(s_ord[jj], (uint32_t)jj) >= thr) ? 1.0f : 0.0f;
        }
        __syncthreads();   // protect s_ckey / s_ncand / s_gmax reuse next row
    }
}

extern "C" void kernel_launch(void* const* d_in, const int* in_sizes, int n_in,
                              void* d_out, int out_size) {
    (void)in_sizes; (void)n_in; (void)out_size;
    const float* scores = (const float*)d_in[0];
    const float* noise  = (const float*)d_in[1];
    const float* tau    = (const float*)d_in[2];
    const int*   k      = (const int*)d_in[3];
    float* out = (float*)d_out;
    st_subset_sampler_kernel<<<GRID, THREADS>>>(scores, noise, tau, k, out);
}

// round 6
// speedup vs baseline: 1.1334x; 1.1304x over previous
#include <cuda_runtime.h>
#include <cstdint>

#define N_NODES   8192
#define THREADS   512
#define GRID      592              // persistent; 4 CTA/SM
#define NBINS     256
#define CAND_MAX  1024
#define NGROUPS   64               // 8-lane group maxima (512 thr / 8)
#define VEC_ITERS (N_NODES / 4 / THREADS)   // 4 float4 per thread

__device__ unsigned int g_row_ctr;          // dynamic row scheduler state

__global__ void init_ctr_kernel() { g_row_ctr = GRID; }

// Monotonic float -> uint mapping (larger float => larger uint). No NaNs in inputs.
__device__ __forceinline__ uint32_t f2ord(float f) {
    uint32_t u = __float_as_uint(f);
    return u ^ ((uint32_t)((int32_t)u >> 31) | 0x80000000u);
}

// Unique 48-bit total-order key: ties in value resolve to the smaller index
// (matching jax.lax.top_k).
__device__ __forceinline__ unsigned long long make_key(uint32_t ord, uint32_t j) {
    return ((unsigned long long)ord << 16) | (unsigned)(N_NODES - 1 - j);
}

// Fallback-only: suffix-sum a 256-bin histogram, pick bin holding krem-th largest.
__device__ __forceinline__ void scan_pick(const uint32_t* hist,
                                          volatile uint32_t* s_cum,
                                          unsigned long long* s_prefix,
                                          int* s_krem)
{
    const int lane = threadIdx.x;           // caller guarantees tid < 32
    uint32_t h[8], suf[8];
    #pragma unroll
    for (int j = 0; j < 8; ++j) h[j] = hist[lane * 8 + j];
    uint32_t acc = 0;
    #pragma unroll
    for (int j = 7; j >= 0; --j) { acc += h[j]; suf[j] = acc; }
    uint32_t run = acc;
    #pragma unroll
    for (int off = 1; off < 32; off <<= 1) {
        uint32_t v = __shfl_down_sync(0xFFFFFFFFu, run, off);
        if (lane + off < 32) run += v;
    }
    const uint32_t above = run - acc;
    #pragma unroll
    for (int j = 0; j < 8; ++j) s_cum[lane * 8 + j] = above + suf[j];
    if (lane == 0) s_cum[NBINS] = 0;
    __syncwarp();
    const uint32_t krem = (uint32_t)(*s_krem);
    #pragma unroll
    for (int j = 0; j < 8; ++j) {
        const int b = lane * 8 + j;
        const uint32_t ge = s_cum[b];
        const uint32_t gt = s_cum[b + 1];
        if (ge >= krem && gt < krem) {
            *s_prefix = (*s_prefix << 8) | (unsigned long long)(uint32_t)b;
            *s_krem   = (int)(krem - gt);
        }
    }
}

__global__ __launch_bounds__(THREADS, 4)
void st_subset_sampler_kernel(const float* __restrict__ scores,
                              const float* __restrict__ noise,
                              const float* __restrict__ tau_p,
                              const int*   __restrict__ k_p,
                              float* __restrict__ out)
{
    __shared__ uint32_t s_ord[N_NODES];            // 32 KB ordered keys
    __shared__ uint32_t s_gmax[NGROUPS];
    __shared__ unsigned long long s_ckey[CAND_MAX];// candidate keys (8 KB)
    __shared__ int      s_ncand;
    __shared__ uint32_t s_t32;
    __shared__ int      s_next;
    // fallback-only state
    __shared__ uint32_t s_hist[NBINS];
    __shared__ uint32_t s_cum[NBINS + 1];
    __shared__ unsigned long long s_prefix;
    __shared__ int      s_krem;

    const int tid = threadIdx.x;
    const float tau = __ldg(tau_p);
    const int   k   = __ldg(k_p);

    // Power-of-two tau => a/tau == a*(1/tau) exactly; mul-then-add matches the
    // reference rounding bit-for-bit. Otherwise exact fdiv fallback.
    const uint32_t tb = __float_as_uint(tau);
    const bool pow2 = ((tb & 0x007FFFFFu) == 0u) &&
                      ((tb & 0x7F800000u) != 0u) &&
                      ((tb & 0x7F800000u) != 0x7F800000u);
    const float rtau = __frcp_rn(tau);

    int row_i = blockIdx.x;                 // first row statically assigned
    while (row_i < N_NODES) {
        const size_t row = (size_t)row_i * N_NODES;
        const float4* sp = reinterpret_cast<const float4*>(scores + row);
        const float4* np = reinterpret_cast<const float4*>(noise  + row);

        if (tid == 0) {
            s_ncand = 0; s_t32 = 0;
            // fetch next row early; ATOMG latency hides under the load phase
            s_next = (int)atomicAdd(&g_row_ctr, 1u);
        }

        // ---- phase 1: streaming load, ord -> smem, per-thread max ----
        uint32_t m = 0;
        if (pow2) {
            #pragma unroll
            for (int i = 0; i < VEC_ITERS; ++i) {
                const int idx = tid + i * THREADS;
                const float4 a = __ldcs(&sp[idx]);
                const float4 b = __ldcs(&np[idx]);
                uint4 o;
                o.x = f2ord(__fadd_rn(__fmul_rn(a.x, rtau), b.x));
                o.y = f2ord(__fadd_rn(__fmul_rn(a.y, rtau), b.y));
                o.z = f2ord(__fadd_rn(__fmul_rn(a.z, rtau), b.z));
                o.w = f2ord(__fadd_rn(__fmul_rn(a.w, rtau), b.w));
                reinterpret_cast<uint4*>(s_ord)[idx] = o;
                m = max(m, max(max(o.x, o.y), max(o.z, o.w)));
            }
        } else {
            #pragma unroll
            for (int i = 0; i < VEC_ITERS; ++i) {
                const int idx = tid + i * THREADS;
                const float4 a = __ldcs(&sp[idx]);
                const float4 b = __ldcs(&np[idx]);
                uint4 o;
                o.x = f2ord(__fadd_rn(__fdiv_rn(a.x, tau), b.x));
                o.y = f2ord(__fadd_rn(__fdiv_rn(a.y, tau), b.y));
                o.z = f2ord(__fadd_rn(__fdiv_rn(a.z, tau), b.z));
                o.w = f2ord(__fadd_rn(__fdiv_rn(a.w, tau), b.w));
                reinterpret_cast<uint4*>(s_ord)[idx] = o;
                m = max(m, max(max(o.x, o.y), max(o.z, o.w)));
            }
        }
        // 8-lane group max -> 64 group maxima
        #pragma unroll
        for (int off = 4; off > 0; off >>= 1)
            m = max(m, __shfl_down_sync(0xFFFFFFFFu, m, off, 8));
        if ((tid & 7) == 0) s_gmax[tid >> 3] = m;
        __syncthreads();

        // ---- phase 2: warp 0 exact-ranks the 64 group maxima ----
        // t32 = k-th largest group max <= true k-th largest element T
        // (the top-k group maxima are k distinct elements, each >= t32).
        if (tid < 32 && k >= 1 && k <= NGROUPS) {
            const uint32_t v0 = s_gmax[tid];
            const uint32_t v1 = s_gmax[tid + 32];
            int r0 = 0, r1 = 0;
            #pragma unroll 8
            for (int j = 0; j < NGROUPS; ++j) {
                const uint32_t w = s_gmax[j];
                r0 += (w > v0) || (w == v0 && j < tid);
                r1 += (w > v1) || (w == v1 && j < tid + 32);
            }
            if (r0 == k - 1) s_t32 = v0;
            if (r1 == k - 1) s_t32 = v1;
        }
        __syncthreads();
        const uint32_t t32 = s_t32;
        const int row_next = s_next;         // safe: bracketed by the two syncs

        // ---- phase 3: fused provisional write + candidate compaction ----
        float4* op = reinterpret_cast<float4*>(out + row);
        #pragma unroll
        for (int i = 0; i < VEC_ITERS; ++i) {
            const int idx = tid + i * THREADS;
            const uint4 o = reinterpret_cast<const uint4*>(s_ord)[idx];
            float4 r;
            r.x = (o.x >= t32) ? 1.0f : 0.0f;
            r.y = (o.y >= t32) ? 1.0f : 0.0f;
            r.z = (o.z >= t32) ? 1.0f : 0.0f;
            r.w = (o.w >= t32) ? 1.0f : 0.0f;
            __stcs(&op[idx], r);             // evict-first: pure write stream
            const uint32_t j = (uint32_t)idx * 4;
            if (o.x >= t32) { int p = atomicAdd(&s_ncand, 1); if (p < CAND_MAX) s_ckey[p] = make_key(o.x, j + 0); }
            if (o.y >= t32) { int p = atomicAdd(&s_ncand, 1); if (p < CAND_MAX) s_ckey[p] = make_key(o.y, j + 1); }
            if (o.z >= t32) { int p = atomicAdd(&s_ncand, 1); if (p < CAND_MAX) s_ckey[p] = make_key(o.z, j + 2); }
            if (o.w >= t32) { int p = atomicAdd(&s_ncand, 1); if (p < CAND_MAX) s_ckey[p] = make_key(o.w, j + 3); }
        }
        __syncthreads();
        const int nc = s_ncand;

        if (nc <= CAND_MAX) {
            // ---- phase 4: O(nc^2) exact rank over candidates (nc ~ k) ----
            // All true top-k have ord >= T >= t32, so they are candidates;
            // keys are unique, so (rank < k) selects exactly the global top-k.
            for (int c = tid; c < nc; c += THREADS) {
                const unsigned long long key = s_ckey[c];
                int rank = 0;
                for (int t = 0; t < nc; ++t)
                    rank += (s_ckey[t] > key);
                const uint32_t j = (uint32_t)(N_NODES - 1) - (uint32_t)(key & 0xFFFFu);
                out[row + j] = (rank < k) ? 1.0f : 0.0f;
            }
        } else {
            // ---- fallback (adversarial inputs only): exact 48-bit radix ----
            if (tid == 0) { s_prefix = 0ull; s_krem = k; }
            for (int d = 0; d < 6; ++d) {
                if (tid < NBINS) s_hist[tid] = 0;
                __syncthreads();
                const unsigned long long pre = s_prefix;
                const int shd = 40 - 8 * d, shp = 48 - 8 * d;
                for (int jj = tid; jj < N_NODES; jj += THREADS) {
                    const unsigned long long key = make_key(s_ord[jj], (uint32_t)jj);
                    if (d == 0 || (key >> shp) == pre)
                        atomicAdd(&s_hist[(uint32_t)(key >> shd) & 0xFFu], 1u);
                }
                __syncthreads();
                if (tid < 32) scan_pick(s_hist, s_cum, &s_prefix, &s_krem);
                __syncthreads();
            }
            const unsigned long long thr = s_prefix;
            for (int jj = tid; jj < N_NODES; jj += THREADS)
                out[row + jj] = (make_key(s_ord[jj], (uint32_t)jj) >= thr) ? 1.0f : 0.0f;
        }
        __syncthreads();   // protect s_ord / s_ckey / s_ncand / s_next reuse
        row_i = row_next;
    }
}

extern "C" void kernel_launch(void* const* d_in, const int* in_sizes, int n_in,
                              void* d_out, int out_size) {
    (void)in_sizes; (void)n_in; (void)out_size;
    const float* scores = (const float*)d_in[0];
    const float* noise  = (const float*)d_in[1];
    const float* tau    = (const float*)d_in[2];
    const int*   k      = (const int*)d_in[3];
    float* out = (float*)d_out;
    init_ctr_kernel<<<1, 1>>>();
    st_subset_sampler_kernel<<<GRID, THREADS>>>(scores, noise, tau, k, out);
}